// round 1
// baseline (speedup 1.0000x reference)
#include <cuda_runtime.h>
#include <cuda_bf16.h>
#include <math.h>

#define N_NODES 8192
#define F_IN    512
#define F_OUT   64
#define ALPHA   0.2f

// scratch (no cudaMalloc allowed)
__device__ float g_wh[N_NODES * F_OUT];
__device__ float g_s1[N_NODES];
__device__ float g_s2[N_NODES];

// ---------------------------------------------------------------------------
// Kernel A: wh = x @ w ; s1 = wh @ a1 ; s2 = wh @ a2
// Block: 256 threads = 4 rows x 64 features
// ---------------------------------------------------------------------------
__global__ void __launch_bounds__(256) wh_kernel(const float* __restrict__ x,
                                                 const float* __restrict__ w,
                                                 const float* __restrict__ a)
{
    __shared__ float xs[4][F_IN];          // 8 KB
    __shared__ float red1[256];
    __shared__ float red2[256];

    const int t    = threadIdx.x;
    const int row0 = blockIdx.x * 4;

    // cooperative load of 4 x-rows (coalesced)
    for (int idx = t; idx < 4 * F_IN; idx += 256) {
        int r = idx >> 9;          // / 512
        int k = idx & (F_IN - 1);
        xs[r][k] = x[(row0 + r) * F_IN + k];
    }
    __syncthreads();

    const int r = t >> 6;          // 0..3
    const int f = t & 63;

    float acc = 0.f;
#pragma unroll 8
    for (int k = 0; k < F_IN; k++)
        acc += xs[r][k] * w[k * F_OUT + f];

    g_wh[(row0 + r) * F_OUT + f] = acc;

    red1[t] = acc * a[f];
    red2[t] = acc * a[F_OUT + f];
    __syncthreads();
    for (int s = 32; s >= 1; s >>= 1) {
        if (f < s) {
            red1[t] += red1[t + s];
            red2[t] += red2[t + s];
        }
        __syncthreads();
    }
    if (f == 0) {
        g_s1[row0 + r] = red1[t];
        g_s2[row0 + r] = red2[t];
    }
}

// ---------------------------------------------------------------------------
// Kernel B: fused masked-softmax attention + P@V, online softmax over j-tiles
// Block: 256 threads, BM=32 rows, BN=64 j per tile.
//   Phase 1: warp w owns rows w*4..w*4+3. Lanes sweep BN in chunks of 32.
//   Phase 2: thread t owns (row = t>>3, features fb = (t&7)*8).
// ---------------------------------------------------------------------------
#define BM 32
#define BN 64

__global__ void __launch_bounds__(256) attn_kernel(const int* __restrict__ adj,
                                                   float* __restrict__ out)
{
    __shared__ float whs[BN][F_OUT];   // 16 KB
    __shared__ float ps[BM][BN + 1];   // padded: kill 4-way bank conflict
    __shared__ float s2s[BN];
    __shared__ float scale_s[BM];
    __shared__ float l_s[BM];

    const int t    = threadIdx.x;
    const int warp = t >> 5;
    const int lane = t & 31;
    const int i0   = blockIdx.x * BM;

    // phase-1 state (per warp: 4 rows)
    float m[4], l[4], s1r[4];
#pragma unroll
    for (int r = 0; r < 4; r++) {
        m[r]   = -INFINITY;
        l[r]   = 0.f;
        s1r[r] = g_s1[i0 + warp * 4 + r];
    }

    // phase-2 state
    const int row2 = t >> 3;
    const int fb   = (t & 7) * 8;
    float acc[8];
#pragma unroll
    for (int k = 0; k < 8; k++) acc[k] = 0.f;

    for (int j0 = 0; j0 < N_NODES; j0 += BN) {
        // ---- load wh tile (contiguous BN*F_OUT floats) + s2 tile ----
        {
            const float4* src = (const float4*)(g_wh + j0 * F_OUT);
            float4*       dst = (float4*)(&whs[0][0]);
#pragma unroll
            for (int idx = t; idx < BN * F_OUT / 4; idx += 256)
                dst[idx] = src[idx];
            if (t < BN) s2s[t] = g_s2[j0 + t];
        }
        __syncthreads();

        // ---- phase 1: masked leaky-relu scores, online softmax ----
#pragma unroll
        for (int r = 0; r < 4; r++) {
            const int row = warp * 4 + r;
            const long gbase = (long)(i0 + row) * N_NODES + j0;
            float mx = -INFINITY;
#pragma unroll
            for (int cc = 0; cc < BN; cc += 32) {
                const int c = cc + lane;
                const int av = adj[gbase + c];
                float e  = s1r[r] + s2s[c];
                float le = e > 0.f ? e : ALPHA * e;
                float v  = (av > 0) ? le : -INFINITY;
                ps[row][c] = v;
                mx = fmaxf(mx, v);
            }
#pragma unroll
            for (int o = 16; o >= 1; o >>= 1)
                mx = fmaxf(mx, __shfl_xor_sync(0xffffffffu, mx, o));

            const float nm = fmaxf(m[r], mx);
            const float sc = (m[r] == nm) ? 1.f : __expf(m[r] - nm);

            float sum = 0.f;
#pragma unroll
            for (int cc = 0; cc < BN; cc += 32) {
                const int c = cc + lane;
                float v = ps[row][c];
                float p = (v == -INFINITY) ? 0.f : __expf(v - nm);
                ps[row][c] = p;
                sum += p;
            }
#pragma unroll
            for (int o = 16; o >= 1; o >>= 1)
                sum += __shfl_xor_sync(0xffffffffu, sum, o);

            l[r] = l[r] * sc + sum;
            m[r] = nm;
            if (lane == 0) scale_s[row] = sc;
        }
        __syncthreads();

        // ---- phase 2: acc = acc*scale + P_tile @ wh_tile ----
        {
            const float sc2 = scale_s[row2];
#pragma unroll
            for (int k = 0; k < 8; k++) acc[k] *= sc2;

#pragma unroll 4
            for (int c = 0; c < BN; c++) {
                const float p = ps[row2][c];
                const float4 w0 = *(const float4*)&whs[c][fb];
                const float4 w1 = *(const float4*)&whs[c][fb + 4];
                acc[0] += p * w0.x;  acc[1] += p * w0.y;
                acc[2] += p * w0.z;  acc[3] += p * w0.w;
                acc[4] += p * w1.x;  acc[5] += p * w1.y;
                acc[6] += p * w1.z;  acc[7] += p * w1.w;
            }
        }
        __syncthreads();   // before next tile overwrites ps/whs
    }

    // publish row denominators
    if (lane == 0) {
#pragma unroll
        for (int r = 0; r < 4; r++) l_s[warp * 4 + r] = l[r];
    }
    __syncthreads();

    // epilogue: divide + ELU-ish activation, write out
    {
        const float linv = 1.f / l_s[row2];
        float* o = out + (long)(i0 + row2) * F_OUT + fb;
#pragma unroll
        for (int k = 0; k < 8; k++) {
            float h = acc[k] * linv;
            o[k] = (h > 0.f) ? h : expm1f(h);
        }
    }
}

// ---------------------------------------------------------------------------
extern "C" void kernel_launch(void* const* d_in, const int* in_sizes, int n_in,
                              void* d_out, int out_size)
{
    const float* x   = (const float*)d_in[0];
    const int*   adj = (const int*)d_in[1];
    const float* w   = (const float*)d_in[2];
    const float* a   = (const float*)d_in[3];
    float*       out = (float*)d_out;

    wh_kernel<<<N_NODES / 4, 256>>>(x, w, a);
    attn_kernel<<<N_NODES / BM, 256>>>(adj, out);
}

// round 2
// speedup vs baseline: 1.7660x; 1.7660x over previous
#include <cuda_runtime.h>
#include <cuda_bf16.h>
#include <math.h>

#define N_NODES 8192
#define F_IN    512
#define F_OUT   64
#define ALPHA   0.2f

#define BM      64
#define BN      64
#define JSPLIT  4
#define JCHUNK  (N_NODES / JSPLIT)   // 2048

// ---- scratch (__device__ globals; no allocation allowed) ----
__device__ float g_wh[N_NODES * F_OUT];
__device__ float g_E1 [N_NODES];   // exp(s1)
__device__ float g_E1p[N_NODES];   // exp(0.2*s1)
__device__ float g_E2 [N_NODES];   // exp(s2)
__device__ float g_E2p[N_NODES];   // exp(0.2*s2)
__device__ float g_pacc[JSPLIT][N_NODES * F_OUT];  // 8 MB partials
__device__ float g_pl  [JSPLIT][N_NODES];

// ---- packed f32x2 helpers (Blackwell dual-FMA; ptxas won't auto-fuse) ----
__device__ __forceinline__ unsigned long long ffma2(unsigned long long a,
                                                    unsigned long long b,
                                                    unsigned long long c) {
    unsigned long long d;
    asm("fma.rn.f32x2 %0, %1, %2, %3;" : "=l"(d) : "l"(a), "l"(b), "l"(c));
    return d;
}
__device__ __forceinline__ unsigned long long packf2(float x) {
    unsigned long long r;
    asm("mov.b64 %0, {%1, %1};" : "=l"(r) : "f"(x));
    return r;
}

// ---------------------------------------------------------------------------
// Kernel A: wh = x @ w ; s1 = wh@a1 ; s2 = wh@a2 ; store factorized exps
// Block: 256 threads = 4 rows x 64 features
// ---------------------------------------------------------------------------
__global__ void __launch_bounds__(256) wh_kernel(const float* __restrict__ x,
                                                 const float* __restrict__ w,
                                                 const float* __restrict__ a)
{
    __shared__ float xs[4][F_IN];
    __shared__ float red1[256];
    __shared__ float red2[256];

    const int t    = threadIdx.x;
    const int row0 = blockIdx.x * 4;

    for (int idx = t; idx < 4 * F_IN; idx += 256) {
        int r = idx >> 9;
        int k = idx & (F_IN - 1);
        xs[r][k] = x[(row0 + r) * F_IN + k];
    }
    __syncthreads();

    const int r = t >> 6;
    const int f = t & 63;

    float acc = 0.f;
#pragma unroll 8
    for (int k = 0; k < F_IN; k++)
        acc += xs[r][k] * w[k * F_OUT + f];

    g_wh[(row0 + r) * F_OUT + f] = acc;

    red1[t] = acc * a[f];
    red2[t] = acc * a[F_OUT + f];
    __syncthreads();
    for (int s = 32; s >= 1; s >>= 1) {
        if (f < s) {
            red1[t] += red1[t + s];
            red2[t] += red2[t + s];
        }
        __syncthreads();
    }
    if (f == 0) {
        const int row = row0 + r;
        float s1 = red1[t], s2 = red2[t];
        g_E1 [row] = __expf(s1);
        g_E1p[row] = __expf(ALPHA * s1);
        g_E2 [row] = __expf(s2);
        g_E2p[row] = __expf(ALPHA * s2);
    }
}

// ---------------------------------------------------------------------------
// Kernel B: partial masked attention (no max needed: scores are tiny vs fp32
// range, and softmax is shift-invariant -> plain sums; split-K over j).
//   p_ij = adj ? (E1i*E2j > 1 ? E1i*E2j : E1pi*E2pj) : 0
//   pacc[i,:] = sum_j p_ij * wh_j ;  pl[i] = sum_j p_ij
// Block: 256 threads. Phase 1: thread t -> row t>>2, cols (t&3)*16..+16.
// Phase 2: thread t -> rows {g, g+32} (g=t>>3), feats (t&7)*8..+8, FFMA2.
// ---------------------------------------------------------------------------
__global__ void __launch_bounds__(256) attn_kernel(const int* __restrict__ adj)
{
    __shared__ __align__(16) float whs[BN][F_OUT];      // 16 KB
    __shared__ __align__(16) float ps[BM][BN + 4];      // 17 KB (pad 4: align + banks)
    __shared__ float E2s[BN], E2ps[BN];

    const int t  = threadIdx.x;
    const int i0 = blockIdx.x * BM;
    const int js = blockIdx.y;
    const int jbase = js * JCHUNK;

    // phase-1 identity
    const int r1 = t >> 2;            // 0..63
    const int cb = (t & 3) * 16;      // 0,16,32,48
    const float e1  = g_E1 [i0 + r1];
    const float e1p = g_E1p[i0 + r1];
    float myl = 0.f;

    // phase-2 identity
    const int g  = t >> 3;            // 0..31 -> rows g, g+32
    const int fb = (t & 7) * 8;       // feature base
    unsigned long long a0[4], a1[4];
#pragma unroll
    for (int k = 0; k < 4; k++) { a0[k] = 0ull; a1[k] = 0ull; }

    for (int jt = 0; jt < JCHUNK; jt += BN) {
        const int j0 = jbase + jt;

        // ---- stage wh tile + exp factors ----
        {
            const float4* src = (const float4*)(g_wh + (size_t)j0 * F_OUT);
            float4*       dst = (float4*)(&whs[0][0]);
#pragma unroll
            for (int idx = t; idx < BN * F_OUT / 4; idx += 256)
                dst[idx] = src[idx];
            if (t < BN) {
                E2s [t] = g_E2 [j0 + t];
                E2ps[t] = g_E2p[j0 + t];
            }
        }
        __syncthreads();

        // ---- phase 1: p tile (pure ALU, adj read once) ----
        {
            const int4* ap = (const int4*)(adj + (size_t)(i0 + r1) * N_NODES + j0 + cb);
#pragma unroll
            for (int k = 0; k < 4; k++) {
                const int4 av = ap[k];
                const int  c  = cb + k * 4;
                float4 pv;
                {
                    float q  = e1  * E2s [c + 0];
                    float qp = e1p * E2ps[c + 0];
                    pv.x = (av.x > 0) ? ((q > 1.f) ? q : qp) : 0.f;
                    q  = e1  * E2s [c + 1];
                    qp = e1p * E2ps[c + 1];
                    pv.y = (av.y > 0) ? ((q > 1.f) ? q : qp) : 0.f;
                    q  = e1  * E2s [c + 2];
                    qp = e1p * E2ps[c + 2];
                    pv.z = (av.z > 0) ? ((q > 1.f) ? q : qp) : 0.f;
                    q  = e1  * E2s [c + 3];
                    qp = e1p * E2ps[c + 3];
                    pv.w = (av.w > 0) ? ((q > 1.f) ? q : qp) : 0.f;
                }
                myl += pv.x + pv.y + pv.z + pv.w;
                *(float4*)&ps[r1][c] = pv;
            }
        }
        __syncthreads();

        // ---- phase 2: acc += P_tile @ wh_tile (packed f32x2 FMA) ----
        {
#pragma unroll 8
            for (int c = 0; c < BN; c++) {
                const unsigned long long pp0 = packf2(ps[g][c]);
                const unsigned long long pp1 = packf2(ps[g + 32][c]);
                const ulonglong2 wA = *(const ulonglong2*)&whs[c][fb];
                const ulonglong2 wB = *(const ulonglong2*)&whs[c][fb + 4];
                a0[0] = ffma2(pp0, wA.x, a0[0]);
                a0[1] = ffma2(pp0, wA.y, a0[1]);
                a0[2] = ffma2(pp0, wB.x, a0[2]);
                a0[3] = ffma2(pp0, wB.y, a0[3]);
                a1[0] = ffma2(pp1, wA.x, a1[0]);
                a1[1] = ffma2(pp1, wA.y, a1[1]);
                a1[2] = ffma2(pp1, wB.x, a1[2]);
                a1[3] = ffma2(pp1, wB.y, a1[3]);
            }
        }
        __syncthreads();
    }

    // ---- write partial row sums (reduce 4 threads/row via shfl) ----
    {
        myl += __shfl_xor_sync(0xffffffffu, myl, 1);
        myl += __shfl_xor_sync(0xffffffffu, myl, 2);
        if ((t & 3) == 0) g_pl[js][i0 + r1] = myl;
    }

    // ---- write partial accumulators (bit layout = 2 consecutive floats) ----
    {
        float* p0 = &g_pacc[js][(size_t)(i0 + g) * F_OUT + fb];
        float* p1 = &g_pacc[js][(size_t)(i0 + g + 32) * F_OUT + fb];
        ((ulonglong2*)p0)[0] = make_ulonglong2(a0[0], a0[1]);
        ((ulonglong2*)p0)[1] = make_ulonglong2(a0[2], a0[3]);
        ((ulonglong2*)p1)[0] = make_ulonglong2(a1[0], a1[1]);
        ((ulonglong2*)p1)[1] = make_ulonglong2(a1[2], a1[3]);
    }
}

// ---------------------------------------------------------------------------
// Kernel C: combine splits, divide by row sum, activation
// ---------------------------------------------------------------------------
__global__ void __launch_bounds__(256) finish_kernel(float* __restrict__ out)
{
    const int idx = blockIdx.x * 256 + threadIdx.x;    // over N*F
    const int i   = idx >> 6;

    float s = 0.f, l = 0.f;
#pragma unroll
    for (int sp = 0; sp < JSPLIT; sp++) {
        s += g_pacc[sp][idx];
        l += g_pl[sp][i];
    }
    const float h = s / l;
    out[idx] = (h > 0.f) ? h : expm1f(h);
}

// ---------------------------------------------------------------------------
extern "C" void kernel_launch(void* const* d_in, const int* in_sizes, int n_in,
                              void* d_out, int out_size)
{
    const float* x   = (const float*)d_in[0];
    const int*   adj = (const int*)d_in[1];
    const float* w   = (const float*)d_in[2];
    const float* a   = (const float*)d_in[3];
    float*       out = (float*)d_out;

    wh_kernel<<<N_NODES / 4, 256>>>(x, w, a);
    attn_kernel<<<dim3(N_NODES / BM, JSPLIT), 256>>>(adj);
    finish_kernel<<<N_NODES * F_OUT / 256, 256>>>(out);
}

// round 3
// speedup vs baseline: 3.0579x; 1.7315x over previous
#include <cuda_runtime.h>
#include <cuda_bf16.h>
#include <math.h>

#define N_NODES 8192
#define F_IN    512
#define F_OUT   64
#define ALPHA   0.2f

#define BM      128                  // rows per attn block
#define BN      64                   // j columns per tile
#define JSPLIT  16
#define JCHUNK  (N_NODES / JSPLIT)   // 512
#define PSTRIDE 68                   // ps/whsT row stride (floats, 16B-aligned pad)

// ---- scratch (__device__ globals; no allocation allowed) ----
__device__ float g_whT[F_OUT][N_NODES];           // 2 MB, transposed wh
__device__ float g_E1 [N_NODES];
__device__ float g_E1p[N_NODES];
__device__ float g_E2 [N_NODES];
__device__ float g_E2p[N_NODES];
__device__ float g_wa [2][F_IN];                  // w@a1, w@a2
__device__ float g_pacc[JSPLIT][N_NODES * F_OUT]; // 32 MB partials
__device__ float g_pl  [JSPLIT][N_NODES];

// ---- packed f32x2 helpers ----
__device__ __forceinline__ unsigned long long ffma2(unsigned long long a,
                                                    unsigned long long b,
                                                    unsigned long long c) {
    unsigned long long d;
    asm("fma.rn.f32x2 %0, %1, %2, %3;" : "=l"(d) : "l"(a), "l"(b), "l"(c));
    return d;
}
__device__ __forceinline__ unsigned long long packf2(float x) {
    unsigned long long r;
    asm("mov.b64 %0, {%1, %1};" : "=l"(r) : "f"(x));
    return r;
}
__device__ __forceinline__ float2 unpackf2(unsigned long long v) {
    float lo, hi;
    asm("mov.b64 {%0, %1}, %2;" : "=f"(lo), "=f"(hi) : "l"(v));
    return make_float2(lo, hi);
}

// ---------------------------------------------------------------------------
// Kernel 0: wa1 = w @ a1, wa2 = w @ a2   (512 x 64 -> 512)
// ---------------------------------------------------------------------------
__global__ void __launch_bounds__(128) wa_kernel(const float* __restrict__ w,
                                                 const float* __restrict__ a)
{
    const int k = blockIdx.x * 128 + threadIdx.x;   // 0..511
    float s1 = 0.f, s2 = 0.f;
#pragma unroll 8
    for (int f = 0; f < F_OUT; f++) {
        const float wv = w[k * F_OUT + f];
        s1 += wv * a[f];
        s2 += wv * a[F_OUT + f];
    }
    g_wa[0][k] = s1;
    g_wa[1][k] = s2;
}

// ---------------------------------------------------------------------------
// Kernel A: wh = x @ w (written transposed to g_whT); s1 = x@wa1, s2 = x@wa2;
// store factorized exps E1/E1p/E2/E2p.
// Block: 256 threads = 16 rowgroups(4 rows) x 16 featgroups(4 feats); BM=64.
// ---------------------------------------------------------------------------
__global__ void __launch_bounds__(256) wh_kernel(const float* __restrict__ x,
                                                 const float* __restrict__ w)
{
    __shared__ __align__(16) float xs[64][68];   // [row][k]
    __shared__ __align__(16) float ws[64][68];   // [k][f]
    __shared__ float wa_s[2][64];

    const int t    = threadIdx.x;
    const int row0 = blockIdx.x * 64;
    const int rgrp = t >> 4;      // 0..15
    const int fgrp = t & 15;      // 0..15
    const int fb   = fgrp * 4;

    unsigned long long acc[4][2];
#pragma unroll
    for (int r = 0; r < 4; r++) { acc[r][0] = 0ull; acc[r][1] = 0ull; }
    float s1a[4] = {0.f, 0.f, 0.f, 0.f};
    float s2a[4] = {0.f, 0.f, 0.f, 0.f};

    for (int k0 = 0; k0 < F_IN; k0 += 64) {
        // stage x tile [64r][64k] and w tile [64k][64f]
#pragma unroll
        for (int idx = t; idx < 64 * 16; idx += 256) {
            const int r  = idx >> 4;
            const int c4 = (idx & 15) * 4;
            *(float4*)&xs[r][c4] = *(const float4*)&x[(size_t)(row0 + r) * F_IN + k0 + c4];
            *(float4*)&ws[r][c4] = *(const float4*)&w[(size_t)(k0 + r) * F_OUT + c4];
        }
        if (t < 64) {
            wa_s[0][t] = g_wa[0][k0 + t];
            wa_s[1][t] = g_wa[1][k0 + t];
        }
        __syncthreads();

#pragma unroll 4
        for (int kk = 0; kk < 64; kk++) {
            const ulonglong2 wp = *(const ulonglong2*)&ws[kk][fb];
            const float wa1 = wa_s[0][kk];
            const float wa2 = wa_s[1][kk];
#pragma unroll
            for (int r = 0; r < 4; r++) {
                const float xv = xs[rgrp * 4 + r][kk];
                const unsigned long long xp = packf2(xv);
                acc[r][0] = ffma2(xp, wp.x, acc[r][0]);
                acc[r][1] = ffma2(xp, wp.y, acc[r][1]);
                if (fgrp == 0) {
                    s1a[r] += xv * wa1;
                    s2a[r] += xv * wa2;
                }
            }
        }
        __syncthreads();
    }

    // write wh transposed: g_whT[f][row]
#pragma unroll
    for (int h = 0; h < 4; h++) {
        float v[4];
#pragma unroll
        for (int r = 0; r < 4; r++) {
            const float2 p = unpackf2(acc[r][h >> 1]);
            v[r] = (h & 1) ? p.y : p.x;
        }
        *(float4*)&g_whT[fb + h][row0 + rgrp * 4] = make_float4(v[0], v[1], v[2], v[3]);
    }

    if (fgrp == 0) {
#pragma unroll
        for (int r = 0; r < 4; r++) {
            const int row = row0 + rgrp * 4 + r;
            g_E1 [row] = __expf(s1a[r]);
            g_E1p[row] = __expf(ALPHA * s1a[r]);
            g_E2 [row] = __expf(s2a[r]);
            g_E2p[row] = __expf(ALPHA * s2a[r]);
        }
    }
}

// ---------------------------------------------------------------------------
// Kernel B: partial masked attention, split-K over j.
//   Phase 1: build P tile (BM x BN) in smem (swizzled), accumulate row sums.
//   Phase 2: acc += P @ WH^T tile, thread tile 8 rows x 4 feats, FFMA2 dot.
// ---------------------------------------------------------------------------
extern __shared__ __align__(16) char smem_buf[];

__global__ void __launch_bounds__(256) attn_kernel(const int* __restrict__ adj)
{
    // smem carve
    float (*ps)[PSTRIDE]   = (float(*)[PSTRIDE])(smem_buf);                    // [BM][68] 34816B
    float (*whsT)[PSTRIDE] = (float(*)[PSTRIDE])(smem_buf + 34816);            // [64][68] 17408B
    float* E2s  = (float*)(smem_buf + 34816 + 17408);                          // 64
    float* E2ps = E2s + 64;                                                    // 64
    float* e1s  = E2ps + 64;                                                   // 128
    float* e1ps = e1s + 128;                                                   // 128
    float* lrow = e1ps + 128;                                                  // 128

    const int t  = threadIdx.x;
    const int i0 = blockIdx.x * BM;
    const int js = blockIdx.y;
    const int jbase = js * JCHUNK;

    // phase-2 identity
    const int rg    = t >> 4;          // 0..15 -> rows rg*8 .. rg*8+7
    const int fgrp  = t & 15;          // 0..15 -> feats fgrp*4 .. +3
    const int prow0 = rg * 8;
    const int px    = (rg & 3) << 2;   // p column XOR swizzle

    unsigned long long accp[8][4];
#pragma unroll
    for (int r = 0; r < 8; r++)
#pragma unroll
        for (int h = 0; h < 4; h++) accp[r][h] = 0ull;

    // per-block constants
    if (t < BM) {
        e1s [t] = g_E1 [i0 + t];
        e1ps[t] = g_E1p[i0 + t];
        lrow[t] = 0.f;
    }

    for (int jt = 0; jt < JCHUNK; jt += BN) {
        const int j0 = jbase + jt;

        // ---- stage whsT tile (64 f x 64 c, swizzled) + E2 factors ----
#pragma unroll
        for (int idx = t; idx < 64 * 16; idx += 256) {
            const int f  = idx >> 4;
            const int c4 = (idx & 15) * 4;
            const float4 v = *(const float4*)&g_whT[f][j0 + c4];
            *(float4*)&whsT[f][c4 ^ (((f >> 3) & 7) << 2)] = v;
        }
        if (t < 64) {
            E2s [t] = g_E2 [j0 + t];
            E2ps[t] = g_E2p[j0 + t];
        }
        __syncthreads();

        // ---- phase 1: P tile + row sums ----
#pragma unroll
        for (int it = 0; it < (BM * BN / 4) / 256; it++) {
            const int idx = t + 256 * it;        // int4 index
            const int row = idx >> 4;
            const int cb  = (idx & 15) * 4;
            const int4 av = *(const int4*)&adj[(size_t)(i0 + row) * N_NODES + j0 + cb];
            const float e1v  = e1s[row];
            const float e1pv = e1ps[row];
            const float4 E2v  = *(const float4*)&E2s[cb];
            const float4 E2pv = *(const float4*)&E2ps[cb];

            float4 pv;
            {
                float q, qp;
                q = e1v * E2v.x;  qp = e1pv * E2pv.x;
                pv.x = (av.x > 0) ? ((q > 1.f) ? q : qp) : 0.f;
                q = e1v * E2v.y;  qp = e1pv * E2pv.y;
                pv.y = (av.y > 0) ? ((q > 1.f) ? q : qp) : 0.f;
                q = e1v * E2v.z;  qp = e1pv * E2pv.z;
                pv.z = (av.z > 0) ? ((q > 1.f) ? q : qp) : 0.f;
                q = e1v * E2v.w;  qp = e1pv * E2pv.w;
                pv.w = (av.w > 0) ? ((q > 1.f) ? q : qp) : 0.f;
            }
            // row-sum: 16 lanes per row
            float s = (pv.x + pv.y) + (pv.z + pv.w);
            s += __shfl_xor_sync(0xffffffffu, s, 1);
            s += __shfl_xor_sync(0xffffffffu, s, 2);
            s += __shfl_xor_sync(0xffffffffu, s, 4);
            s += __shfl_xor_sync(0xffffffffu, s, 8);
            if ((t & 15) == 0) lrow[row] += s;

            *(float4*)&ps[row][cb ^ (((row >> 3) & 3) << 2)] = pv;
        }
        __syncthreads();

        // ---- phase 2: acc += P @ WH^T ----
#pragma unroll 2
        for (int cc = 0; cc < BN; cc += 4) {
            ulonglong2 pvv[8];
#pragma unroll
            for (int r = 0; r < 8; r++)
                pvv[r] = *(const ulonglong2*)&ps[prow0 + r][cc ^ px];
            ulonglong2 wvv[4];
#pragma unroll
            for (int h = 0; h < 4; h++) {
                const int f = fgrp * 4 + h;
                wvv[h] = *(const ulonglong2*)&whsT[f][cc ^ (((f >> 3) & 7) << 2)];
            }
#pragma unroll
            for (int r = 0; r < 8; r++)
#pragma unroll
                for (int h = 0; h < 4; h++) {
                    accp[r][h] = ffma2(pvv[r].x, wvv[h].x, accp[r][h]);
                    accp[r][h] = ffma2(pvv[r].y, wvv[h].y, accp[r][h]);
                }
        }
        __syncthreads();
    }

    // ---- write partial row sums + accumulators ----
    if (t < BM) g_pl[js][i0 + t] = lrow[t];

#pragma unroll
    for (int r = 0; r < 8; r++) {
        const int row = i0 + prow0 + r;
        float4 o;
        float2 p0 = unpackf2(accp[r][0]);
        float2 p1 = unpackf2(accp[r][1]);
        float2 p2 = unpackf2(accp[r][2]);
        float2 p3 = unpackf2(accp[r][3]);
        o.x = p0.x + p0.y;
        o.y = p1.x + p1.y;
        o.z = p2.x + p2.y;
        o.w = p3.x + p3.y;
        *(float4*)&g_pacc[js][(size_t)row * F_OUT + fgrp * 4] = o;
    }
}

// ---------------------------------------------------------------------------
// Kernel C: combine splits, divide by row sum, activation
// ---------------------------------------------------------------------------
__global__ void __launch_bounds__(256) finish_kernel(float* __restrict__ out)
{
    const int idx = blockIdx.x * 256 + threadIdx.x;    // over N*F
    const int i   = idx >> 6;

    float s = 0.f, l = 0.f;
#pragma unroll
    for (int sp = 0; sp < JSPLIT; sp++) {
        s += g_pacc[sp][idx];
        l += g_pl[sp][i];
    }
    const float h = s / l;
    out[idx] = (h > 0.f) ? h : expm1f(h);
}

// ---------------------------------------------------------------------------
extern "C" void kernel_launch(void* const* d_in, const int* in_sizes, int n_in,
                              void* d_out, int out_size)
{
    const float* x   = (const float*)d_in[0];
    const int*   adj = (const int*)d_in[1];
    const float* w   = (const float*)d_in[2];
    const float* a   = (const float*)d_in[3];
    float*       out = (float*)d_out;

    static int smem_set = -1;
    const int ATTN_SMEM = 34816 + 17408 + (64 + 64 + 128 + 128 + 128) * 4;
    if (smem_set < 0) {
        cudaFuncSetAttribute(attn_kernel,
                             cudaFuncAttributeMaxDynamicSharedMemorySize, ATTN_SMEM);
        smem_set = 1;
    }

    wa_kernel<<<F_IN / 128, 128>>>(w, a);
    wh_kernel<<<N_NODES / 64, 256>>>(x, w);
    attn_kernel<<<dim3(N_NODES / BM, JSPLIT), 256, ATTN_SMEM>>>(adj);
    finish_kernel<<<N_NODES * F_OUT / 256, 256>>>(out);
}

// round 4
// speedup vs baseline: 3.9312x; 1.2856x over previous
#include <cuda_runtime.h>
#include <cuda_bf16.h>
#include <math.h>

#define N_NODES 8192
#define F_IN    512
#define F_OUT   64
#define ALPHA   0.2f

#define BM      128                  // rows per attn block
#define BN      64                   // j columns per tile
#define JSPLIT  4
#define JCHUNK  (N_NODES / JSPLIT)   // 2048
#define PSTRIDE 68                   // ps row stride (floats, 16B-aligned pad)

// ---- scratch (__device__ globals; no allocation allowed) ----
__device__ float g_wh[N_NODES * F_OUT];           // row-major wh
__device__ float g_E1 [N_NODES];
__device__ float g_E1p[N_NODES];
__device__ float g_E2 [N_NODES];
__device__ float g_E2p[N_NODES];
__device__ float g_wa [2][F_IN];                  // w@a1, w@a2
__device__ float g_pacc[JSPLIT][N_NODES * F_OUT]; // partials
__device__ float g_pl  [JSPLIT][N_NODES];

// ---- packed f32x2 helpers ----
__device__ __forceinline__ unsigned long long ffma2(unsigned long long a,
                                                    unsigned long long b,
                                                    unsigned long long c) {
    unsigned long long d;
    asm("fma.rn.f32x2 %0, %1, %2, %3;" : "=l"(d) : "l"(a), "l"(b), "l"(c));
    return d;
}
__device__ __forceinline__ unsigned long long packf2(float x) {
    unsigned long long r;
    asm("mov.b64 %0, {%1, %1};" : "=l"(r) : "f"(x));
    return r;
}
__device__ __forceinline__ float2 unpackf2(unsigned long long v) {
    float lo, hi;
    asm("mov.b64 {%0, %1}, %2;" : "=f"(lo), "=f"(hi) : "l"(v));
    return make_float2(lo, hi);
}

// ---------------------------------------------------------------------------
// Kernel 0: wa1 = w @ a1, wa2 = w @ a2   (512 x 64 -> 512)
// ---------------------------------------------------------------------------
__global__ void __launch_bounds__(128) wa_kernel(const float* __restrict__ w,
                                                 const float* __restrict__ a)
{
    const int k = blockIdx.x * 128 + threadIdx.x;   // 0..511
    float s1 = 0.f, s2 = 0.f;
#pragma unroll 8
    for (int f = 0; f < F_OUT; f++) {
        const float wv = w[k * F_OUT + f];
        s1 += wv * a[f];
        s2 += wv * a[F_OUT + f];
    }
    g_wa[0][k] = s1;
    g_wa[1][k] = s2;
}

// ---------------------------------------------------------------------------
// Kernel A: wh = x @ w (row-major); s1 = x@wa1, s2 = x@wa2; store exps.
// Block: 256 threads = 16 rowgroups(4 rows) x 16 featgroups(4 feats); 64 rows.
// ---------------------------------------------------------------------------
__global__ void __launch_bounds__(256) wh_kernel(const float* __restrict__ x,
                                                 const float* __restrict__ w)
{
    __shared__ __align__(16) float xs[64][68];   // [row][k]
    __shared__ __align__(16) float ws[64][68];   // [k][f]
    __shared__ float wa_s[2][64];

    const int t    = threadIdx.x;
    const int row0 = blockIdx.x * 64;
    const int rgrp = t >> 4;      // 0..15
    const int fgrp = t & 15;      // 0..15
    const int fb   = fgrp * 4;

    unsigned long long acc[4][2];
#pragma unroll
    for (int r = 0; r < 4; r++) { acc[r][0] = 0ull; acc[r][1] = 0ull; }
    float s1a[4] = {0.f, 0.f, 0.f, 0.f};
    float s2a[4] = {0.f, 0.f, 0.f, 0.f};

    for (int k0 = 0; k0 < F_IN; k0 += 64) {
#pragma unroll
        for (int idx = t; idx < 64 * 16; idx += 256) {
            const int r  = idx >> 4;
            const int c4 = (idx & 15) * 4;
            *(float4*)&xs[r][c4] = *(const float4*)&x[(size_t)(row0 + r) * F_IN + k0 + c4];
            *(float4*)&ws[r][c4] = *(const float4*)&w[(size_t)(k0 + r) * F_OUT + c4];
        }
        if (t < 64) {
            wa_s[0][t] = g_wa[0][k0 + t];
            wa_s[1][t] = g_wa[1][k0 + t];
        }
        __syncthreads();

#pragma unroll 4
        for (int kk = 0; kk < 64; kk++) {
            const ulonglong2 wp = *(const ulonglong2*)&ws[kk][fb];
            const float wa1 = wa_s[0][kk];
            const float wa2 = wa_s[1][kk];
#pragma unroll
            for (int r = 0; r < 4; r++) {
                const float xv = xs[rgrp * 4 + r][kk];
                const unsigned long long xp = packf2(xv);
                acc[r][0] = ffma2(xp, wp.x, acc[r][0]);
                acc[r][1] = ffma2(xp, wp.y, acc[r][1]);
                if (fgrp == 0) {
                    s1a[r] += xv * wa1;
                    s2a[r] += xv * wa2;
                }
            }
        }
        __syncthreads();
    }

    // write wh row-major
#pragma unroll
    for (int r = 0; r < 4; r++) {
        const float2 p0 = unpackf2(acc[r][0]);
        const float2 p1 = unpackf2(acc[r][1]);
        *(float4*)&g_wh[(size_t)(row0 + rgrp * 4 + r) * F_OUT + fb] =
            make_float4(p0.x, p0.y, p1.x, p1.y);
    }

    if (fgrp == 0) {
#pragma unroll
        for (int r = 0; r < 4; r++) {
            const int row = row0 + rgrp * 4 + r;
            g_E1 [row] = __expf(s1a[r]);
            g_E1p[row] = __expf(ALPHA * s1a[r]);
            g_E2 [row] = __expf(s2a[r]);
            g_E2p[row] = __expf(ALPHA * s2a[r]);
        }
    }
}

// ---------------------------------------------------------------------------
// Kernel B: partial masked attention, split-K over j.
//   Phase 1: build P tile (BM x BN) in smem, accumulate row sums.
//   Phase 2: acc += P @ WH tile; whs is c-major so w loads are contiguous
//   (conflict-free); P broadcast; FFMA2 pairs along f.
// Thread tile: 8 rows x 4 feats. rg = t>>4, fgrp = t&15.
// ---------------------------------------------------------------------------
extern __shared__ __align__(16) char smem_buf[];

__global__ void __launch_bounds__(256, 2) attn_kernel(const int* __restrict__ adj)
{
    // smem carve
    float (*ps)[PSTRIDE] = (float(*)[PSTRIDE])(smem_buf);            // [BM][68] 34816B
    float (*whs)[F_OUT]  = (float(*)[F_OUT])(smem_buf + 34816);      // [BN][64] 16384B
    float* E2s  = (float*)(smem_buf + 34816 + 16384);                // 64
    float* E2ps = E2s + 64;                                          // 64
    float* e1s  = E2ps + 64;                                         // 128
    float* e1ps = e1s + 128;                                         // 128
    float* lrow = e1ps + 128;                                        // 128

    const int t  = threadIdx.x;
    const int i0 = blockIdx.x * BM;
    const int js = blockIdx.y;
    const int jbase = js * JCHUNK;

    const int rg    = t >> 4;          // 0..15 -> rows rg*8 .. rg*8+7
    const int fgrp  = t & 15;          // 0..15 -> feats fgrp*4 .. +3
    const int prow0 = rg * 8;
    const int fb    = fgrp * 4;

    unsigned long long accp[8][2];
#pragma unroll
    for (int r = 0; r < 8; r++) { accp[r][0] = 0ull; accp[r][1] = 0ull; }

    if (t < BM) {
        e1s [t] = g_E1 [i0 + t];
        e1ps[t] = g_E1p[i0 + t];
        lrow[t] = 0.f;
    }

    for (int jt = 0; jt < JCHUNK; jt += BN) {
        const int j0 = jbase + jt;

        // ---- stage wh tile (c-major, contiguous copy) + E2 factors ----
        {
            const float4* src = (const float4*)(g_wh + (size_t)j0 * F_OUT);
            float4*       dst = (float4*)(&whs[0][0]);
#pragma unroll
            for (int idx = t; idx < BN * F_OUT / 4; idx += 256)
                dst[idx] = src[idx];
            if (t < 64) {
                E2s [t] = g_E2 [j0 + t];
                E2ps[t] = g_E2p[j0 + t];
            }
        }
        __syncthreads();

        // ---- phase 1: P tile + row sums ----
#pragma unroll
        for (int it = 0; it < (BM * BN / 4) / 256; it++) {
            const int idx = t + 256 * it;        // int4 index
            const int row = idx >> 4;
            const int cb  = (idx & 15) * 4;
            const int4 av = *(const int4*)&adj[(size_t)(i0 + row) * N_NODES + j0 + cb];
            const float e1v  = e1s[row];
            const float e1pv = e1ps[row];
            const float4 E2v  = *(const float4*)&E2s[cb];
            const float4 E2pv = *(const float4*)&E2ps[cb];

            float4 pv;
            {
                float q, qp;
                q = e1v * E2v.x;  qp = e1pv * E2pv.x;
                pv.x = (av.x > 0) ? ((q > 1.f) ? q : qp) : 0.f;
                q = e1v * E2v.y;  qp = e1pv * E2pv.y;
                pv.y = (av.y > 0) ? ((q > 1.f) ? q : qp) : 0.f;
                q = e1v * E2v.z;  qp = e1pv * E2pv.z;
                pv.z = (av.z > 0) ? ((q > 1.f) ? q : qp) : 0.f;
                q = e1v * E2v.w;  qp = e1pv * E2pv.w;
                pv.w = (av.w > 0) ? ((q > 1.f) ? q : qp) : 0.f;
            }
            float s = (pv.x + pv.y) + (pv.z + pv.w);
            s += __shfl_xor_sync(0xffffffffu, s, 1);
            s += __shfl_xor_sync(0xffffffffu, s, 2);
            s += __shfl_xor_sync(0xffffffffu, s, 4);
            s += __shfl_xor_sync(0xffffffffu, s, 8);
            if ((t & 15) == 0) lrow[row] += s;

            *(float4*)&ps[row][cb] = pv;
        }
        __syncthreads();

        // ---- phase 2: acc += P @ WH (FFMA2 pairs along f) ----
#pragma unroll
        for (int cc = 0; cc < BN; cc += 4) {
            ulonglong2 wv[4];
#pragma unroll
            for (int j = 0; j < 4; j++)
                wv[j] = *(const ulonglong2*)&whs[cc + j][fb];
#pragma unroll
            for (int r = 0; r < 8; r++) {
                const float4 p4 = *(const float4*)&ps[prow0 + r][cc];
                const unsigned long long p0 = packf2(p4.x);
                const unsigned long long p1 = packf2(p4.y);
                const unsigned long long p2 = packf2(p4.z);
                const unsigned long long p3 = packf2(p4.w);
                accp[r][0] = ffma2(p0, wv[0].x, accp[r][0]);
                accp[r][1] = ffma2(p0, wv[0].y, accp[r][1]);
                accp[r][0] = ffma2(p1, wv[1].x, accp[r][0]);
                accp[r][1] = ffma2(p1, wv[1].y, accp[r][1]);
                accp[r][0] = ffma2(p2, wv[2].x, accp[r][0]);
                accp[r][1] = ffma2(p2, wv[2].y, accp[r][1]);
                accp[r][0] = ffma2(p3, wv[3].x, accp[r][0]);
                accp[r][1] = ffma2(p3, wv[3].y, accp[r][1]);
            }
        }
        __syncthreads();
    }

    // ---- write partial row sums + accumulators ----
    if (t < BM) g_pl[js][i0 + t] = lrow[t];

#pragma unroll
    for (int r = 0; r < 8; r++) {
        const int row = i0 + prow0 + r;
        const float2 q0 = unpackf2(accp[r][0]);
        const float2 q1 = unpackf2(accp[r][1]);
        *(float4*)&g_pacc[js][(size_t)row * F_OUT + fb] =
            make_float4(q0.x, q0.y, q1.x, q1.y);
    }
}

// ---------------------------------------------------------------------------
// Kernel C: combine splits, divide by row sum, activation
// ---------------------------------------------------------------------------
__global__ void __launch_bounds__(256) finish_kernel(float* __restrict__ out)
{
    const int idx = blockIdx.x * 256 + threadIdx.x;    // over N*F
    const int i   = idx >> 6;

    float s = 0.f, l = 0.f;
#pragma unroll
    for (int sp = 0; sp < JSPLIT; sp++) {
        s += g_pacc[sp][idx];
        l += g_pl[sp][i];
    }
    const float h = s / l;
    out[idx] = (h > 0.f) ? h : expm1f(h);
}

// ---------------------------------------------------------------------------
extern "C" void kernel_launch(void* const* d_in, const int* in_sizes, int n_in,
                              void* d_out, int out_size)
{
    const float* x   = (const float*)d_in[0];
    const int*   adj = (const int*)d_in[1];
    const float* w   = (const float*)d_in[2];
    const float* a   = (const float*)d_in[3];
    float*       out = (float*)d_out;

    static int smem_set = -1;
    const int ATTN_SMEM = 34816 + 16384 + (64 + 64 + 128 + 128 + 128) * 4;
    if (smem_set < 0) {
        cudaFuncSetAttribute(attn_kernel,
                             cudaFuncAttributeMaxDynamicSharedMemorySize, ATTN_SMEM);
        smem_set = 1;
    }

    wa_kernel<<<F_IN / 128, 128>>>(w, a);
    wh_kernel<<<N_NODES / 64, 256>>>(x, w);
    attn_kernel<<<dim3(N_NODES / BM, JSPLIT), 256, ATTN_SMEM>>>(adj);
    finish_kernel<<<N_NODES * F_OUT / 256, 256>>>(out);
}

// round 7
// speedup vs baseline: 6.2176x; 1.5816x over previous
#include <cuda_runtime.h>
#include <cuda_bf16.h>
#include <math.h>
#include <stdint.h>

#define N_NODES 8192
#define F_IN    512
#define F_OUT   64
#define ALPHA   0.2f

#define BM      128
#define BN      64
#define JSPLIT  4
#define JCHUNK  (N_NODES / JSPLIT)   // 2048
#define NTILES  (JCHUNK / BN)        // 32

// ---- scratch (__device__ globals; no allocation allowed) ----
__device__ float g_E1 [N_NODES];
__device__ float g_E1p[N_NODES];
__device__ float g_E2 [N_NODES];
__device__ float g_E2p[N_NODES];
__device__ float g_wa [2][F_IN];
__device__ __nv_bfloat16 g_whT_hi[F_OUT][N_NODES];   // wh transposed, hi part
__device__ __nv_bfloat16 g_whT_lo[F_OUT][N_NODES];   // wh transposed, lo part
__device__ float g_pacc[JSPLIT][N_NODES * F_OUT];
__device__ float g_pl  [JSPLIT][N_NODES];

// ---- packed f32x2 helpers ----
__device__ __forceinline__ unsigned long long ffma2(unsigned long long a,
                                                    unsigned long long b,
                                                    unsigned long long c) {
    unsigned long long d;
    asm("fma.rn.f32x2 %0, %1, %2, %3;" : "=l"(d) : "l"(a), "l"(b), "l"(c));
    return d;
}
__device__ __forceinline__ unsigned long long packf2(float x) {
    unsigned long long r;
    asm("mov.b64 %0, {%1, %1};" : "=l"(r) : "f"(x));
    return r;
}
__device__ __forceinline__ float2 unpackf2(unsigned long long v) {
    float lo, hi;
    asm("mov.b64 {%0, %1}, %2;" : "=f"(lo), "=f"(hi) : "l"(v));
    return make_float2(lo, hi);
}
__device__ __forceinline__ uint32_t smem_to_u32(const void* p) {
    uint32_t a;
    asm("{ .reg .u64 tmp; cvta.to.shared.u64 tmp, %1; cvt.u32.u64 %0, tmp; }"
        : "=r"(a) : "l"(p));
    return a;
}

// ---- ldmatrix / mma.sync (base sm_103-legal, runs on tensor cores) ----
#define LDSM_X4(r, addr) \
    asm volatile("ldmatrix.sync.aligned.m8n8.x4.shared.b16 {%0,%1,%2,%3}, [%4];" \
        : "=r"((r)[0]), "=r"((r)[1]), "=r"((r)[2]), "=r"((r)[3]) : "r"(addr))

#define MMA_BF16(d, a, b0, b1) \
    asm volatile("mma.sync.aligned.m16n8k16.row.col.f32.bf16.bf16.f32 " \
        "{%0,%1,%2,%3}, {%4,%5,%6,%7}, {%8,%9}, {%0,%1,%2,%3};" \
        : "+f"((d)[0]), "+f"((d)[1]), "+f"((d)[2]), "+f"((d)[3]) \
        : "r"((a)[0]), "r"((a)[1]), "r"((a)[2]), "r"((a)[3]), "r"(b0), "r"(b1))

// SW128-style swizzle on byte offsets (row stride 128B): b ^ ((b>>3)&0x70)
__device__ __forceinline__ uint32_t sw128(uint32_t off) {
    return off ^ ((off >> 3) & 0x70);
}

// ---------------------------------------------------------------------------
// Kernel 0: wa1 = w @ a1, wa2 = w @ a2
// ---------------------------------------------------------------------------
__global__ void __launch_bounds__(128) wa_kernel(const float* __restrict__ w,
                                                 const float* __restrict__ a)
{
    const int k = blockIdx.x * 128 + threadIdx.x;
    float s1 = 0.f, s2 = 0.f;
#pragma unroll 8
    for (int f = 0; f < F_OUT; f++) {
        const float wv = w[k * F_OUT + f];
        s1 += wv * a[f];
        s2 += wv * a[F_OUT + f];
    }
    g_wa[0][k] = s1;
    g_wa[1][k] = s2;
}

// ---------------------------------------------------------------------------
// Kernel A: wh = x @ w; s1 = x@wa1, s2 = x@wa2; store exps + bf16 hi/lo whT.
// ---------------------------------------------------------------------------
__global__ void __launch_bounds__(256) wh_kernel(const float* __restrict__ x,
                                                 const float* __restrict__ w)
{
    __shared__ __align__(16) float xs[64][68];
    __shared__ __align__(16) float ws[64][68];
    __shared__ float wa_s[2][64];

    const int t    = threadIdx.x;
    const int row0 = blockIdx.x * 64;
    const int rgrp = t >> 4;
    const int fgrp = t & 15;
    const int fb   = fgrp * 4;

    unsigned long long acc[4][2];
#pragma unroll
    for (int r = 0; r < 4; r++) { acc[r][0] = 0ull; acc[r][1] = 0ull; }
    float s1a[4] = {0.f, 0.f, 0.f, 0.f};
    float s2a[4] = {0.f, 0.f, 0.f, 0.f};

    for (int k0 = 0; k0 < F_IN; k0 += 64) {
#pragma unroll
        for (int idx = t; idx < 64 * 16; idx += 256) {
            const int r  = idx >> 4;
            const int c4 = (idx & 15) * 4;
            *(float4*)&xs[r][c4] = *(const float4*)&x[(size_t)(row0 + r) * F_IN + k0 + c4];
            *(float4*)&ws[r][c4] = *(const float4*)&w[(size_t)(k0 + r) * F_OUT + c4];
        }
        if (t < 64) {
            wa_s[0][t] = g_wa[0][k0 + t];
            wa_s[1][t] = g_wa[1][k0 + t];
        }
        __syncthreads();

#pragma unroll 4
        for (int kk = 0; kk < 64; kk++) {
            const ulonglong2 wp = *(const ulonglong2*)&ws[kk][fb];
            const float wa1 = wa_s[0][kk];
            const float wa2 = wa_s[1][kk];
#pragma unroll
            for (int r = 0; r < 4; r++) {
                const float xv = xs[rgrp * 4 + r][kk];
                const unsigned long long xp = packf2(xv);
                acc[r][0] = ffma2(xp, wp.x, acc[r][0]);
                acc[r][1] = ffma2(xp, wp.y, acc[r][1]);
                if (fgrp == 0) {
                    s1a[r] += xv * wa1;
                    s2a[r] += xv * wa2;
                }
            }
        }
        __syncthreads();
    }

    // write whT as bf16 hi/lo (transposed)
#pragma unroll
    for (int r = 0; r < 4; r++) {
        const int row = row0 + rgrp * 4 + r;
        const float2 p0 = unpackf2(acc[r][0]);
        const float2 p1 = unpackf2(acc[r][1]);
        float v[4] = {p0.x, p0.y, p1.x, p1.y};
#pragma unroll
        for (int h = 0; h < 4; h++) {
            __nv_bfloat16 hi = __float2bfloat16_rn(v[h]);
            __nv_bfloat16 lo = __float2bfloat16_rn(v[h] - __bfloat162float(hi));
            g_whT_hi[fb + h][row] = hi;
            g_whT_lo[fb + h][row] = lo;
        }
    }

    if (fgrp == 0) {
#pragma unroll
        for (int r = 0; r < 4; r++) {
            const int row = row0 + rgrp * 4 + r;
            g_E1 [row] = __expf(s1a[r]);
            g_E1p[row] = __expf(ALPHA * s1a[r]);
            g_E2 [row] = __expf(s2a[r]);
            g_E2p[row] = __expf(ALPHA * s2a[r]);
        }
    }
}

// ---------------------------------------------------------------------------
// Kernel B: masked attention. Phase 1 builds P tile (fp32 -> bf16 hi/lo,
// SW128-swizzled smem). Phase 2: every warp does ldmatrix + mma.sync bf16
// (3-term compensated product) into persistent fp32 register accumulators.
// Warp w owns rows [w*16, w*16+16) x all 64 features.
// ---------------------------------------------------------------------------
#define SM_PS_HI   0                     // 16 KB (128 rows x 128B)
#define SM_PS_LO   16384                 // 16 KB
#define SM_WH_HI   32768                 // 8 KB  (64 f-rows x 128B)
#define SM_WH_LO   40960                 // 8 KB
#define SM_E2      49152                 // 64 f
#define SM_E2P     (49152 + 256)
#define SM_E1      (49152 + 512)         // 128 f
#define SM_E1P     (49152 + 1024)
#define ATTN_SMEM  (49152 + 1536)

extern __shared__ __align__(128) char smem[];

__global__ void __launch_bounds__(256, 2) attn_kernel(const int* __restrict__ adj)
{
    const uint32_t smem_u = smem_to_u32(smem);
    const int t    = threadIdx.x;
    const int wid  = t >> 5;
    const int lane = t & 31;
    const int i0   = blockIdx.x * BM;
    const int js   = blockIdx.y;
    const int jbase = js * JCHUNK;
    const int rw   = wid * 16;        // warp's row base within tile

    float* e1s  = (float*)(smem + SM_E1);
    float* e1ps = (float*)(smem + SM_E1P);
    float* E2s  = (float*)(smem + SM_E2);
    float* E2ps = (float*)(smem + SM_E2P);

    if (t < 128) {
        e1s [t] = g_E1 [i0 + t];
        e1ps[t] = g_E1p[i0 + t];
    }

    float acc[8][4];
#pragma unroll
    for (int n = 0; n < 8; n++)
#pragma unroll
        for (int k = 0; k < 4; k++) acc[n][k] = 0.f;

    float myl[8];
#pragma unroll
    for (int k = 0; k < 8; k++) myl[k] = 0.f;

    // precomputed ldmatrix lane-address components
    const int arow   = rw + (lane & 15);
    const int achnk0 = lane >> 4;                       // 0/1 -> +16B half of k-step
    const int bfrow0 = ((lane >> 4) << 3) + (lane & 7); // f within 16-group
    const int bchnk0 = (lane >> 3) & 1;

    for (int tt = 0; tt < NTILES; tt++) {
        const int j0 = jbase + tt * BN;

        // ---- stage whT hi/lo tiles (SW128 swizzled) + E2 factors ----
#pragma unroll
        for (int idx = t; idx < 512; idx += 256) {
            const int f   = idx >> 3;
            const int c16 = (idx & 7) * 16;
            const uint32_t sw = sw128(f * 128 + c16);
            *(float4*)(smem + SM_WH_HI + sw) =
                *(const float4*)((const char*)&g_whT_hi[f][j0] + c16);
            *(float4*)(smem + SM_WH_LO + sw) =
                *(const float4*)((const char*)&g_whT_lo[f][j0] + c16);
        }
        if (t < 64) {
            E2s [t] = g_E2 [j0 + t];
            E2ps[t] = g_E2p[j0 + t];
        }
        __syncthreads();

        // ---- phase 1: P tile -> bf16 hi/lo swizzled smem ----
#pragma unroll
        for (int it = 0; it < 8; it++) {
            const int row = (t >> 4) + 16 * it;
            const int cb  = (t & 15) * 4;
            const int4 av = *(const int4*)&adj[(size_t)(i0 + row) * N_NODES + j0 + cb];
            const float e1v  = e1s[row];
            const float e1pv = e1ps[row];
            const float4 E2v  = *(const float4*)&E2s[cb];
            const float4 E2pv = *(const float4*)&E2ps[cb];

            float4 pv;
            {
                float q, qp;
                q = e1v * E2v.x;  qp = e1pv * E2pv.x;
                pv.x = (av.x > 0) ? ((q > 1.f) ? q : qp) : 0.f;
                q = e1v * E2v.y;  qp = e1pv * E2pv.y;
                pv.y = (av.y > 0) ? ((q > 1.f) ? q : qp) : 0.f;
                q = e1v * E2v.z;  qp = e1pv * E2pv.z;
                pv.z = (av.z > 0) ? ((q > 1.f) ? q : qp) : 0.f;
                q = e1v * E2v.w;  qp = e1pv * E2pv.w;
                pv.w = (av.w > 0) ? ((q > 1.f) ? q : qp) : 0.f;
            }
            myl[it] += (pv.x + pv.y) + (pv.z + pv.w);

            __nv_bfloat16 bx = __float2bfloat16_rn(pv.x);
            __nv_bfloat16 by = __float2bfloat16_rn(pv.y);
            __nv_bfloat16 bz = __float2bfloat16_rn(pv.z);
            __nv_bfloat16 bw = __float2bfloat16_rn(pv.w);
            __nv_bfloat16 lx = __float2bfloat16_rn(pv.x - __bfloat162float(bx));
            __nv_bfloat16 ly = __float2bfloat16_rn(pv.y - __bfloat162float(by));
            __nv_bfloat16 lz = __float2bfloat16_rn(pv.z - __bfloat162float(bz));
            __nv_bfloat16 lw = __float2bfloat16_rn(pv.w - __bfloat162float(bw));

            uint2 hv, lv;
            hv.x = (uint32_t)__bfloat16_as_ushort(bx) | ((uint32_t)__bfloat16_as_ushort(by) << 16);
            hv.y = (uint32_t)__bfloat16_as_ushort(bz) | ((uint32_t)__bfloat16_as_ushort(bw) << 16);
            lv.x = (uint32_t)__bfloat16_as_ushort(lx) | ((uint32_t)__bfloat16_as_ushort(ly) << 16);
            lv.y = (uint32_t)__bfloat16_as_ushort(lz) | ((uint32_t)__bfloat16_as_ushort(lw) << 16);

            const uint32_t sw = sw128(row * 128 + cb * 2);
            *(uint2*)(smem + SM_PS_HI + sw) = hv;
            *(uint2*)(smem + SM_PS_LO + sw) = lv;
        }
        __syncthreads();

        // ---- phase 2: acc += P @ WH^T via mma.sync (hi*hi + lo*hi + hi*lo) ----
#pragma unroll
        for (int ks = 0; ks < 4; ks++) {
            // A fragments (P rows rw..rw+15, k-step ks)
            const int achunk = ks * 2 + achnk0;
            const uint32_t aoff = sw128((uint32_t)arow * 128 + achunk * 16);
            uint32_t ah[4], al[4];
            LDSM_X4(ah, smem_u + SM_PS_HI + aoff);
            LDSM_X4(al, smem_u + SM_PS_LO + aoff);

#pragma unroll
            for (int np = 0; np < 4; np++) {     // pairs of 8-wide n-steps
                const int f = np * 16 + bfrow0;
                const int bchunk = ks * 2 + bchnk0;
                const uint32_t boff = sw128((uint32_t)f * 128 + bchunk * 16);
                uint32_t bh[4], bl[4];
                LDSM_X4(bh, smem_u + SM_WH_HI + boff);
                LDSM_X4(bl, smem_u + SM_WH_LO + boff);

                MMA_BF16(acc[2 * np],     ah, bh[0], bh[1]);
                MMA_BF16(acc[2 * np],     al, bh[0], bh[1]);
                MMA_BF16(acc[2 * np],     ah, bl[0], bl[1]);
                MMA_BF16(acc[2 * np + 1], ah, bh[2], bh[3]);
                MMA_BF16(acc[2 * np + 1], al, bh[2], bh[3]);
                MMA_BF16(acc[2 * np + 1], ah, bl[2], bl[3]);
            }
        }
        __syncthreads();
    }

    // ---- row sums: reduce 16 threads per row ----
#pragma unroll
    for (int it = 0; it < 8; it++) {
        float s = myl[it];
        s += __shfl_xor_sync(0xffffffffu, s, 1);
        s += __shfl_xor_sync(0xffffffffu, s, 2);
        s += __shfl_xor_sync(0xffffffffu, s, 4);
        s += __shfl_xor_sync(0xffffffffu, s, 8);
        if ((t & 15) == 0) g_pl[js][i0 + (t >> 4) + 16 * it] = s;
    }

    // ---- write accumulators (mma D fragment layout) ----
    {
        const int r0 = i0 + rw + (lane >> 2);
        const int nc = (lane & 3) * 2;
#pragma unroll
        for (int ns = 0; ns < 8; ns++) {
            float* base = &g_pacc[js][(size_t)r0 * F_OUT + ns * 8 + nc];
            *(float2*)base                 = make_float2(acc[ns][0], acc[ns][1]);
            *(float2*)(base + 8 * F_OUT)   = make_float2(acc[ns][2], acc[ns][3]);
        }
    }
}

// ---------------------------------------------------------------------------
// Kernel C: combine splits, divide by row sum, activation
// ---------------------------------------------------------------------------
__global__ void __launch_bounds__(256) finish_kernel(float* __restrict__ out)
{
    const int idx = blockIdx.x * 256 + threadIdx.x;
    const int i   = idx >> 6;

    float s = 0.f, l = 0.f;
#pragma unroll
    for (int sp = 0; sp < JSPLIT; sp++) {
        s += g_pacc[sp][idx];
        l += g_pl[sp][i];
    }
    const float h = s / l;
    out[idx] = (h > 0.f) ? h : expm1f(h);
}

// ---------------------------------------------------------------------------
extern "C" void kernel_launch(void* const* d_in, const int* in_sizes, int n_in,
                              void* d_out, int out_size)
{
    const float* x   = (const float*)d_in[0];
    const int*   adj = (const int*)d_in[1];
    const float* w   = (const float*)d_in[2];
    const float* a   = (const float*)d_in[3];
    float*       out = (float*)d_out;

    static int smem_set = -1;
    if (smem_set < 0) {
        cudaFuncSetAttribute(attn_kernel,
                             cudaFuncAttributeMaxDynamicSharedMemorySize, ATTN_SMEM);
        smem_set = 1;
    }

    wa_kernel<<<F_IN / 128, 128>>>(w, a);
    wh_kernel<<<N_NODES / 64, 256>>>(x, w);
    attn_kernel<<<dim3(N_NODES / BM, JSPLIT), 256, ATTN_SMEM>>>(adj);
    finish_kernel<<<N_NODES * F_OUT / 256, 256>>>(out);
}